// round 6
// baseline (speedup 1.0000x reference)
#include <cuda_runtime.h>
#include <math.h>

#define Dm     256
#define Kc     128
#define NTOK   131072
#define TM     128                 // tokens per tile
#define DC     32                  // D-chunk per smem stage
#define PA     132                 // A-tile pitch
#define NTILES (NTOK / TM)         // 1024
#define NTHR   512
#define MAXCTA 160

// output layout (float32, tuple order flattened+concatenated)
#define OFF_Q    ((size_t)1)
#define OFF_PERP ((size_t)1 + (size_t)NTOK * Dm)
#define OFF_ENC  (OFF_PERP + 1)
#define OFF_IDX  (OFF_ENC + (size_t)NTOK * Kc)

__device__ int   g_hist[MAXCTA * Kc];
__device__ float g_partials[MAXCTA];
__device__ int   g_done = 0;

union F2 { float2 f; unsigned long long u; };

__device__ __forceinline__ void fma2(unsigned long long& c, unsigned long long a, unsigned long long b) {
    asm("fma.rn.f32x2 %0, %1, %2, %0;" : "+l"(c) : "l"(a), "l"(b));
}

// smem floats: As 2*DC*PA=8448, Bs 32768, e2s 128, xn2s 128, red 512,
//              sidx 128, chist 128, ticket 4
#define SMEM_FLOATS (2*DC*PA + Dm*Kc + Kc + TM + NTHR + TM + Kc + 4)
#define SMEM_BYTES  (SMEM_FLOATS * 4)

extern __shared__ float smem[];

__global__ void __launch_bounds__(NTHR, 1) vq_kernel(
    const float* __restrict__ inp,
    const float* __restrict__ emb,
    float* __restrict__ out,
    int ncta)
{
    float* As    = smem;
    float* Bs    = smem + 2 * DC * PA;
    float* e2s   = Bs + Dm * Kc;
    float* xn2s  = e2s + Kc;
    float* red   = xn2s + TM;
    int*   sidx  = (int*)(red + NTHR);
    int*   chist = sidx + TM;
    int*   ticket = chist + Kc;

    const int tid = threadIdx.x;
    const int tx  = tid & 15;          // code group (codes 4tx..4tx+3, 64+4tx..)
    const int ty  = tid >> 4;          // token group: tokens 4ty..4ty+3  (0..31)
    const int lf4 = tid & 7;           // staging: float4 slot in 32-float chunk
    const int lt  = tid >> 3;          // staging: token lane 0..63
    const int cta = blockIdx.x;

    if (tid < Kc) chist[tid] = 0;

    // ---- stage codebook, swizzled: slot(code,d) = (code>>2) ^ ((d>>2)&31) ----
    for (int i = tid; i < Kc * (Dm / 4); i += NTHR) {
        int code = i >> 6;
        int f4   = i & 63;
        float4 v = *(const float4*)(emb + code * Dm + f4 * 4);
        int slot = (code >> 2) ^ (f4 & 31);
        float* p = Bs + (f4 * 4) * Kc + (slot << 2) + (code & 3);
        p[0]      = v.x;
        p[Kc]     = v.y;
        p[2 * Kc] = v.z;
        p[3 * Kc] = v.w;
    }
    __syncthreads();

    // ---- ||e_k||^2 from smem (4 threads per code) ----
    {
        int code = tid >> 2, part = tid & 3;
        int c2 = code >> 2, cl = code & 3;
        float s = 0.f;
        #pragma unroll 8
        for (int i = 0; i < 64; i++) {
            int d = part * 64 + i;
            int slot = c2 ^ ((d >> 2) & 31);
            float v = Bs[d * Kc + (slot << 2) + cl];
            s = fmaf(v, v, s);
        }
        s += __shfl_xor_sync(0xffffffffu, s, 1);
        s += __shfl_xor_sync(0xffffffffu, s, 2);
        if (part == 0) e2s[code] = s;
    }
    __syncthreads();

    float lsum = 0.f;

    // ================= persistent tile loop =================
    for (int tile = cta; tile < NTILES; tile += ncta) {
        const int tb = tile * TM;
        float4 r[2];
        float  xsq[2] = {0.f, 0.f};

        // ---- chunk 0: load + stage + x^2 ----
        #pragma unroll
        for (int q = 0; q < 2; q++)
            r[q] = *(const float4*)(inp + (size_t)(tb + lt + 64 * q) * Dm + lf4 * 4);
        #pragma unroll
        for (int q = 0; q < 2; q++) {
            int tok = lt + 64 * q;
            As[(lf4 * 4 + 0) * PA + tok] = r[q].x;
            As[(lf4 * 4 + 1) * PA + tok] = r[q].y;
            As[(lf4 * 4 + 2) * PA + tok] = r[q].z;
            As[(lf4 * 4 + 3) * PA + tok] = r[q].w;
            float s = r[q].x * r[q].x;
            s = fmaf(r[q].y, r[q].y, s);
            s = fmaf(r[q].z, r[q].z, s);
            xsq[q] += fmaf(r[q].w, r[q].w, s);
        }
        __syncthreads();

        // acc[token][code-pair]: 4 tokens x 4 pairs (8 codes)
        unsigned long long acc[4][4];
        #pragma unroll
        for (int t = 0; t < 4; t++)
            #pragma unroll
            for (int cp = 0; cp < 4; cp++) acc[t][cp] = 0ull;

        #pragma unroll 1
        for (int c = 0; c < Dm / DC; c++) {
            if (c < Dm / DC - 1) {
                #pragma unroll
                for (int q = 0; q < 2; q++)
                    r[q] = *(const float4*)(inp + (size_t)(tb + lt + 64 * q) * Dm
                                            + (c + 1) * DC + lf4 * 4);
            }
            const float* Ac = As + (c & 1) * DC * PA;
            #pragma unroll 4
            for (int k = 0; k < DC; k++) {
                float4 a = *(const float4*)(Ac + k * PA + ty * 4);
                int d  = c * DC + k;
                int sl = (tx ^ ((d >> 2) & 31)) << 2;
                float4 b0 = *(const float4*)(Bs + d * Kc + sl);
                float4 b1 = *(const float4*)(Bs + d * Kc + (sl ^ 64));
                F2 ad[4];
                ad[0].f = make_float2(a.x, a.x);
                ad[1].f = make_float2(a.y, a.y);
                ad[2].f = make_float2(a.z, a.z);
                ad[3].f = make_float2(a.w, a.w);
                F2 bp[4];
                bp[0].f = make_float2(b0.x, b0.y);
                bp[1].f = make_float2(b0.z, b0.w);
                bp[2].f = make_float2(b1.x, b1.y);
                bp[3].f = make_float2(b1.z, b1.w);
                #pragma unroll
                for (int t = 0; t < 4; t++)
                    #pragma unroll
                    for (int cp = 0; cp < 4; cp++)
                        fma2(acc[t][cp], ad[t].u, bp[cp].u);
            }
            if (c < Dm / DC - 1) {
                float* An = As + ((c + 1) & 1) * DC * PA;
                #pragma unroll
                for (int q = 0; q < 2; q++) {
                    int tok = lt + 64 * q;
                    An[(lf4 * 4 + 0) * PA + tok] = r[q].x;
                    An[(lf4 * 4 + 1) * PA + tok] = r[q].y;
                    An[(lf4 * 4 + 2) * PA + tok] = r[q].z;
                    An[(lf4 * 4 + 3) * PA + tok] = r[q].w;
                    float s = r[q].x * r[q].x;
                    s = fmaf(r[q].y, r[q].y, s);
                    s = fmaf(r[q].z, r[q].z, s);
                    xsq[q] += fmaf(r[q].w, r[q].w, s);
                }
            }
            __syncthreads();
        }

        // ---- ||x||^2 per token (reduce over 8 lf4 lanes) ----
        #pragma unroll
        for (int q = 0; q < 2; q++) {
            float s = xsq[q];
            s += __shfl_xor_sync(0xffffffffu, s, 1);
            s += __shfl_xor_sync(0xffffffffu, s, 2);
            s += __shfl_xor_sync(0xffffffffu, s, 4);
            if (lf4 == 0) xn2s[lt + 64 * q] = s;
        }

        // ---- argmin per token ----
        float e2r[8];
        #pragma unroll
        for (int j = 0; j < 4; j++) {
            e2r[j]     = e2s[tx * 4 + j];
            e2r[4 + j] = e2s[64 + tx * 4 + j];
        }
        float bsum = 0.f;
        #pragma unroll
        for (int t = 0; t < 4; t++) {
            float best = 3.402823466e38f;
            int   bi   = 0;
            #pragma unroll
            for (int cp = 0; cp < 4; cp++) {
                F2 a; a.u = acc[t][cp];
                int code_lo = (cp < 2) ? (tx * 4 + 2 * cp) : (64 + tx * 4 + 2 * (cp - 2));
                float s0 = fmaf(-2.0f, a.f.x, e2r[2 * cp]);
                float s1 = fmaf(-2.0f, a.f.y, e2r[2 * cp + 1]);
                if (s0 < best) { best = s0; bi = code_lo; }
                if (s1 < best) { best = s1; bi = code_lo + 1; }
            }
            #pragma unroll
            for (int m = 1; m < 16; m <<= 1) {
                float ov = __shfl_xor_sync(0xffffffffu, best, m);
                int   oi = __shfl_xor_sync(0xffffffffu, bi,   m);
                if (ov < best || (ov == best && oi < bi)) { best = ov; bi = oi; }
            }
            if (tx == 0) { sidx[ty * 4 + t] = bi; bsum += best; }
        }
        __syncthreads();

        // loss: ||e-x||^2 = best + ||x||^2
        if (tx == 0) {
            #pragma unroll
            for (int t = 0; t < 4; t++) lsum += xn2s[ty * 4 + t];
            lsum += bsum;
        }

        // histogram
        if (tid < TM) atomicAdd(&chist[sidx[tid]], 1);

        // ---- quantized (region starts at elem 1 -> scalar stores) ----
        float* out_q = out + OFF_Q;
        #pragma unroll 1
        for (int i = tid; i < TM * (Dm / 4); i += NTHR) {   // 16 iters
            int tok = i >> 6, f4 = i & 63;
            int k2 = sidx[tok];
            float4 e = *(const float4*)(emb + k2 * Dm + f4 * 4);
            float* qp = out_q + (size_t)(tb + tok) * Dm + f4 * 4;
            qp[0] = e.x; qp[1] = e.y; qp[2] = e.z; qp[3] = e.w;
        }

        // ---- one-hot encodings (region start == 2 mod 4 -> float2 ok) ----
        float* out_e = out + OFF_ENC;
        #pragma unroll 1
        for (int i = tid; i < TM * (Kc / 4); i += NTHR) {   // 8 iters
            int tok = i >> 5, f4 = i & 31;
            int k2 = sidx[tok];
            int d0 = f4 * 4;
            float2 v01, v23;
            v01.x = (d0 + 0 == k2) ? 1.f : 0.f;
            v01.y = (d0 + 1 == k2) ? 1.f : 0.f;
            v23.x = (d0 + 2 == k2) ? 1.f : 0.f;
            v23.y = (d0 + 3 == k2) ? 1.f : 0.f;
            float* ep = out_e + (size_t)(tb + tok) * Kc + d0;
            *(float2*)(ep)     = v01;
            *(float2*)(ep + 2) = v23;
        }

        if (tid < TM) out[OFF_IDX + tb + tid] = (float)sidx[tid];
        __syncthreads();   // protect sidx/xn2s/As for next tile
    }

    // ================= per-CTA results =================
    red[tid] = lsum;
    __syncthreads();
    #pragma unroll
    for (int s = NTHR / 2; s > 0; s >>= 1) {
        if (tid < s) red[tid] += red[tid + s];
        __syncthreads();
    }
    if (tid == 0) g_partials[cta] = red[0];
    if (tid < Kc) g_hist[cta * Kc + tid] = chist[tid];

    __syncthreads();
    __threadfence();
    if (tid == 0) ticket[0] = atomicAdd(&g_done, 1);
    __syncthreads();

    // ================= last CTA: loss + perplexity =================
    if (ticket[0] == ncta - 1) {
        __threadfence();
        float term = 0.f;
        if (tid < Kc) {
            int cnt = 0;
            for (int b = 0; b < ncta; b++) cnt += g_hist[b * Kc + tid];
            float p = (float)cnt / (float)NTOK;
            term = p * logf(p + 1e-10f);
        }
        red[tid] = term;
        __syncthreads();
        #pragma unroll
        for (int s = NTHR / 2; s > 0; s >>= 1) {
            if (tid < s) red[tid] += red[tid + s];
            __syncthreads();
        }
        float perp = expf(-red[0]);
        __syncthreads();

        red[tid] = (tid < ncta) ? g_partials[tid] : 0.f;
        __syncthreads();
        #pragma unroll
        for (int s = NTHR / 2; s > 0; s >>= 1) {
            if (tid < s) red[tid] += red[tid + s];
            __syncthreads();
        }
        if (tid == 0) {
            out[0]        = 0.25f * red[0] / ((float)NTOK * (float)Dm);
            out[OFF_PERP] = perp;
            g_done = 0;                     // reset for next graph replay
        }
    }
}

// ---------------- launch ----------------
extern "C" void kernel_launch(void* const* d_in, const int* in_sizes, int n_in,
                              void* d_out, int out_size) {
    const float* inp = (const float*)d_in[0];   // [64,2048,256] f32
    const float* emb = (const float*)d_in[1];   // [128,256]     f32
    float* out = (float*)d_out;

    int nsm = 0;
    cudaDeviceGetAttribute(&nsm, cudaDevAttrMultiProcessorCount, 0);
    if (nsm <= 0) nsm = 148;
    if (nsm > MAXCTA) nsm = MAXCTA;
    if (nsm > NTILES) nsm = NTILES;

    cudaFuncSetAttribute(vq_kernel,
                         cudaFuncAttributeMaxDynamicSharedMemorySize, SMEM_BYTES);

    vq_kernel<<<nsm, NTHR, SMEM_BYTES>>>(inp, emb, out, nsm);
}